// round 6
// baseline (speedup 1.0000x reference)
#include <cuda_runtime.h>
#include <cuda_fp16.h>
#include <math.h>
#include <stdint.h>

// Problem constants
#define NTOK   8192
#define DIM    1024
#define ODIM   1024
#define NEXP   8
#define TOPK   2
#define ASSIGN (NTOK*TOPK)

// GEMM tiling
#define BM 128
#define BN 256
#define BK 64
#define NSTAGE (DIM/BK)                 // 16
#define MAX_TILES (ASSIGN/BM + NEXP)    // 136
#define GEMM_THREADS 256                // 8 warps: 2 (m) x 4 (n), warp tile 64x64

// ---- smem layout (bytes) ----
#define A_STRIDE_B 144
#define A_BUF      (128*A_STRIDE_B)     // 18432
#define A_OFF      0
#define B_STRIDE_B 528
#define B_BUF      (64*B_STRIDE_B)      // 33792
#define B_OFF      (2*A_BUF)            // 36864
#define TOK_OFF    (B_OFF + 2*B_BUF)    // 104448
#define GATE_OFF   (TOK_OFF + 512)
#define BE_OFF     (GATE_OFF + 512)
#define SMEM_TOTAL (BE_OFF + 1024)      // 106496

// ---------------- device scratch ----------------
__device__ int   g_topk_idx[ASSIGN];
__device__ float g_topk_gate[ASSIGN];
__device__ int   g_counts[NEXP];
__device__ int   g_cursor[NEXP];
__device__ int   g_tile_expert[MAX_TILES];
__device__ int   g_tile_row[MAX_TILES];
__device__ int   g_tile_rows[MAX_TILES];
__device__ int   g_num_tiles;
__device__ int   g_assign_token[ASSIGN];
__device__ float g_assign_gate[ASSIGN];
__device__ float g_Wgt[NEXP*DIM];        // transposed gate weight [e][d]
// fp16 operands (x: [tok][k], W: [e][k][n])
__device__ __half g_xf[NTOK*DIM];
__device__ __half g_Wf[NEXP*DIM*ODIM];

// ---------------- PTX helpers (baseline PTX only) ----------------
__device__ __forceinline__ uint32_t smem_u32(const void* p) {
    uint32_t a;
    asm("{ .reg .u64 t; cvta.to.shared.u64 t, %1; cvt.u32.u64 %0, t; }" : "=r"(a) : "l"(p));
    return a;
}
__device__ __forceinline__ void cp16(uint32_t dst, const void* src) {
    asm volatile("cp.async.cg.shared.global [%0], [%1], 16;" :: "r"(dst), "l"(src));
}
#define CP_COMMIT() asm volatile("cp.async.commit_group;" ::: "memory")
#define CP_WAIT0()  asm volatile("cp.async.wait_group 0;" ::: "memory")

__device__ __forceinline__ void ldsm_x4(uint32_t* r, uint32_t addr) {
    asm volatile("ldmatrix.sync.aligned.m8n8.x4.shared.b16 {%0,%1,%2,%3}, [%4];"
        : "=r"(r[0]), "=r"(r[1]), "=r"(r[2]), "=r"(r[3]) : "r"(addr));
}
__device__ __forceinline__ void ldsm_x4_t(uint32_t* r, uint32_t addr) {
    asm volatile("ldmatrix.sync.aligned.m8n8.x4.trans.shared.b16 {%0,%1,%2,%3}, [%4];"
        : "=r"(r[0]), "=r"(r[1]), "=r"(r[2]), "=r"(r[3]) : "r"(addr));
}
__device__ __forceinline__ void mma_f16(float* c, const uint32_t* a, const uint32_t* b) {
    asm volatile(
        "mma.sync.aligned.m16n8k16.row.col.f32.f16.f16.f32 "
        "{%0,%1,%2,%3}, {%4,%5,%6,%7}, {%8,%9}, {%0,%1,%2,%3};"
        : "+f"(c[0]), "+f"(c[1]), "+f"(c[2]), "+f"(c[3])
        : "r"(a[0]), "r"(a[1]), "r"(a[2]), "r"(a[3]), "r"(b[0]), "r"(b[1]));
}

// ---------------- init: zero counters, transpose Wg, zero output ----------------
__global__ void init_kernel(const float* __restrict__ Wg,
                            float* __restrict__ out, int out_elems)
{
    int t = blockIdx.x * blockDim.x + threadIdx.x;
    if (t < NEXP) g_counts[t] = 0;
    if (t == 0)   g_num_tiles = 0;
    if (t < NEXP * DIM) {                    // transpose Wg[d][e] -> Wgt[e][d]
        int e = t / DIM, d = t % DIM;
        g_Wgt[t] = Wg[d * NEXP + e];
    }
    int stride = gridDim.x * blockDim.x;
    float4 z = make_float4(0.f, 0.f, 0.f, 0.f);
    for (int i = t; i < out_elems / 4; i += stride)
        reinterpret_cast<float4*>(out)[i] = z;
}

// ---------------- convert x / We to fp16 ----------------
__global__ void convx_kernel(const float* __restrict__ x)
{
    int i = blockIdx.x * blockDim.x + threadIdx.x;
    if (i >= NTOK * DIM / 4) return;
    float4 v = reinterpret_cast<const float4*>(x)[i];
    __half2* o = reinterpret_cast<__half2*>(g_xf);
    o[i*2+0] = __floats2half2_rn(v.x, v.y);
    o[i*2+1] = __floats2half2_rn(v.z, v.w);
}
__global__ void convw_kernel(const float* __restrict__ We)
{
    int i = blockIdx.x * blockDim.x + threadIdx.x;
    if (i >= NEXP * DIM * ODIM / 4) return;
    float4 v = reinterpret_cast<const float4*>(We)[i];
    __half2* o = reinterpret_cast<__half2*>(g_Wf);
    o[i*2+0] = __floats2half2_rn(v.x, v.y);
    o[i*2+1] = __floats2half2_rn(v.z, v.w);
}

// ---------------- gating: one warp per token, split-D x4 ----------------
// lane = c*8 + e : expert e, D-chunk c (256 elems). Wgt gives float4 weight
// loads. Shuffle-sum over chunks, then the validated 8-lane top-2 butterfly.
__global__ void gate_kernel(const float* __restrict__ x,
                            const float* __restrict__ bg)
{
    int lane = threadIdx.x & 31;
    int wrp  = threadIdx.x >> 5;
    int n    = blockIdx.x * 8 + wrp;
    int e    = lane & 7;
    int c    = lane >> 3;

    const float* xr = x + (size_t)n * DIM + c * 256;
    const float* wr = g_Wgt + e * DIM + c * 256;

    float a0 = 0.f, a1 = 0.f, a2 = 0.f, a3 = 0.f;
    #pragma unroll 4
    for (int d = 0; d < 256; d += 16) {
        float4 x0 = *reinterpret_cast<const float4*>(xr + d);
        float4 w0 = *reinterpret_cast<const float4*>(wr + d);
        float4 x1 = *reinterpret_cast<const float4*>(xr + d + 4);
        float4 w1 = *reinterpret_cast<const float4*>(wr + d + 4);
        float4 x2 = *reinterpret_cast<const float4*>(xr + d + 8);
        float4 w2 = *reinterpret_cast<const float4*>(wr + d + 8);
        float4 x3 = *reinterpret_cast<const float4*>(xr + d + 12);
        float4 w3 = *reinterpret_cast<const float4*>(wr + d + 12);
        a0 += x0.x*w0.x + x0.y*w0.y + x0.z*w0.z + x0.w*w0.w;
        a1 += x1.x*w1.x + x1.y*w1.y + x1.z*w1.z + x1.w*w1.w;
        a2 += x2.x*w2.x + x2.y*w2.y + x2.z*w2.z + x2.w*w2.w;
        a3 += x3.x*w3.x + x3.y*w3.y + x3.z*w3.z + x3.w*w3.w;
    }
    float v = (a0 + a1) + (a2 + a3);
    // sum the 4 chunks (lanes differing in bits 3,4)
    v += __shfl_xor_sync(0xffffffffu, v, 8);
    v += __shfl_xor_sync(0xffffffffu, v, 16);
    v += bg[e];

    int idx = e;
    float bv = v;  int bi = idx;
    #pragma unroll
    for (int off = 4; off; off >>= 1) {
        float ov = __shfl_xor_sync(0xffffffffu, bv, off);
        int   oi = __shfl_xor_sync(0xffffffffu, bi, off);
        if (ov > bv || (ov == bv && oi < bi)) { bv = ov; bi = oi; }
    }
    float sv = (idx == bi) ? -INFINITY : v;
    int   si = idx;
    #pragma unroll
    for (int off = 4; off; off >>= 1) {
        float ov = __shfl_xor_sync(0xffffffffu, sv, off);
        int   oi = __shfl_xor_sync(0xffffffffu, si, off);
        if (ov > sv || (ov == sv && oi < si)) { sv = ov; si = oi; }
    }
    if (lane == 0) {
        float w1 = 1.0f / (1.0f + expf(sv - bv));
        float w2 = 1.0f - w1;
        g_topk_idx [n * 2 + 0] = bi;
        g_topk_idx [n * 2 + 1] = si;
        g_topk_gate[n * 2 + 0] = w1;
        g_topk_gate[n * 2 + 1] = w2;
        atomicAdd(&g_counts[bi], 1);
        atomicAdd(&g_counts[si], 1);
    }
}

// ---------------- scheduler + scatter ----------------
__global__ void sched_kernel()
{
    if (threadIdx.x != 0 || blockIdx.x != 0) return;
    int off = 0, nt = 0;
    for (int e = 0; e < NEXP; e++) {
        g_cursor[e] = off;
        int c = g_counts[e];
        for (int r = 0; r < c; r += BM) {
            g_tile_expert[nt] = e;
            g_tile_row[nt]    = off + r;
            g_tile_rows[nt]   = min(BM, c - r);
            nt++;
        }
        off += c;
    }
    g_num_tiles = nt;
}

__global__ void scatter_kernel()
{
    int n = blockIdx.x * blockDim.x + threadIdx.x;
    if (n >= NTOK) return;
    #pragma unroll
    for (int k = 0; k < TOPK; k++) {
        int   e = g_topk_idx [n * 2 + k];
        float g = g_topk_gate[n * 2 + k];
        int pos = atomicAdd(&g_cursor[e], 1);
        g_assign_token[pos] = n;
        g_assign_gate[pos]  = g;
    }
}

// ---------------- fp16 HMMA grouped GEMM ----------------
__device__ __forceinline__ void load_stage(uint32_t sm, int k0, int buf,
                                           int e, int n0, const int* s_tok)
{
    int t = threadIdx.x;
    uint32_t abase = sm + A_OFF + buf * A_BUF;
    uint32_t bbase = sm + B_OFF + buf * B_BUF;
    #pragma unroll
    for (int c = t; c < 1024; c += GEMM_THREADS) {
        int r = c >> 3, c8 = c & 7;
        int tok = s_tok[r];
        size_t off = ((size_t)tok << 10) + k0 + (c8 << 3);
        cp16(abase + r * A_STRIDE_B + c8 * 16, g_xf + off);
    }
    #pragma unroll
    for (int c = t; c < 2048; c += GEMM_THREADS) {
        int kr = c >> 5, c32 = c & 31;
        size_t off = ((size_t)(e * DIM + k0 + kr) << 10) + n0 + (c32 << 3);
        cp16(bbase + kr * B_STRIDE_B + c32 * 16, g_Wf + off);
    }
    CP_COMMIT();
}

__global__ __launch_bounds__(GEMM_THREADS)
void moe_gemm_kernel(const float* __restrict__ be, float* __restrict__ out)
{
    extern __shared__ char dsm[];
    uint32_t sm = smem_u32(dsm);
    int tile = blockIdx.x;
    if (tile >= g_num_tiles) return;
    int e    = g_tile_expert[tile];
    int row0 = g_tile_row[tile];
    int rows = g_tile_rows[tile];
    int n0   = blockIdx.y * BN;
    int t    = threadIdx.x;
    int wid  = t >> 5, lane = t & 31;
    int wm   = wid & 1;
    int wn   = wid >> 1;

    int*   s_tok  = (int*)  (dsm + TOK_OFF);
    float* s_gate = (float*)(dsm + GATE_OFF);
    float* s_be   = (float*)(dsm + BE_OFF);

    if (t < BM) {
        if (t < rows) {
            s_tok [t] = g_assign_token[row0 + t];
            s_gate[t] = g_assign_gate [row0 + t];
        } else {
            s_tok [t] = 0;
            s_gate[t] = 0.f;
        }
    }
    s_be[t] = be[e * ODIM + n0 + t];
    __syncthreads();

    float acc[4][8][4];
    #pragma unroll
    for (int i = 0; i < 4; i++)
        #pragma unroll
        for (int j = 0; j < 8; j++)
            #pragma unroll
            for (int q = 0; q < 4; q++) acc[i][j][q] = 0.f;

    load_stage(sm, 0, 0, e, n0, s_tok);

    #pragma unroll 1
    for (int s = 0; s < NSTAGE; s++) {
        int buf = s & 1;
        CP_WAIT0();
        __syncthreads();
        if (s + 1 < NSTAGE)
            load_stage(sm, (s + 1) * BK, buf ^ 1, e, n0, s_tok);

        uint32_t abase = sm + A_OFF + buf * A_BUF;
        uint32_t bbase = sm + B_OFF + buf * B_BUF;
        #pragma unroll
        for (int ks = 0; ks < 4; ks++) {
            uint32_t a[4][4], b[8][2];
            #pragma unroll
            for (int mi = 0; mi < 4; mi++) {
                int row = wm * 64 + mi * 16 + (lane & 15);
                ldsm_x4(a[mi], abase + row * A_STRIDE_B + ks * 32 + (lane >> 4) * 16);
            }
            #pragma unroll
            for (int np = 0; np < 4; np++) {
                int krow = ks * 16 + (lane & 15);
                int ncol = wn * 64 + np * 16 + (lane >> 4) * 8;
                uint32_t tb[4];
                ldsm_x4_t(tb, bbase + krow * B_STRIDE_B + ncol * 2);
                b[np*2][0]   = tb[0]; b[np*2][1]   = tb[1];
                b[np*2+1][0] = tb[2]; b[np*2+1][1] = tb[3];
            }
            #pragma unroll
            for (int mi = 0; mi < 4; mi++)
                #pragma unroll
                for (int ni = 0; ni < 8; ni++)
                    mma_f16(acc[mi][ni], a[mi], b[ni]);
        }
        __syncthreads();
    }

    int r_in  = lane >> 2;
    int c_in  = (lane & 3) * 2;
    #pragma unroll
    for (int mi = 0; mi < 4; mi++) {
        int rbase = wm * 64 + mi * 16 + r_in;
        int tok0 = s_tok[rbase];     float g0 = s_gate[rbase];
        int tok1 = s_tok[rbase + 8]; float g1 = s_gate[rbase + 8];
        float* o0 = out + (size_t)tok0 * ODIM + n0;
        float* o1 = out + (size_t)tok1 * ODIM + n0;
        #pragma unroll
        for (int ni = 0; ni < 8; ni++) {
            int col = wn * 64 + ni * 8 + c_in;
            float b0 = s_be[col], b1 = s_be[col + 1];
            if (g0 != 0.f) {
                atomicAdd(o0 + col,     g0 * (acc[mi][ni][0] + b0));
                atomicAdd(o0 + col + 1, g0 * (acc[mi][ni][1] + b1));
            }
            if (g1 != 0.f) {
                atomicAdd(o1 + col,     g1 * (acc[mi][ni][2] + b0));
                atomicAdd(o1 + col + 1, g1 * (acc[mi][ni][3] + b1));
            }
        }
    }
}

// ---------------- launch ----------------
extern "C" void kernel_launch(void* const* d_in, const int* in_sizes, int n_in,
                              void* d_out, int out_size)
{
    const float* x  = (const float*)d_in[0];
    const float* We = (const float*)d_in[1];
    const float* be = (const float*)d_in[2];
    const float* Wg = (const float*)d_in[3];
    const float* bg = (const float*)d_in[4];
    float* out = (float*)d_out;

    static int smem_set = 0;
    if (!smem_set) {
        cudaFuncSetAttribute(moe_gemm_kernel,
                             cudaFuncAttributeMaxDynamicSharedMemorySize, SMEM_TOTAL);
        smem_set = 1;
    }

    init_kernel<<<512, 256>>>(Wg, out, out_size);
    convx_kernel<<<(NTOK * DIM / 4 + 255) / 256, 256>>>(x);
    convw_kernel<<<(NEXP * DIM * ODIM / 4 + 255) / 256, 256>>>(We);
    gate_kernel<<<NTOK / 8, 256>>>(x, bg);
    sched_kernel<<<1, 32>>>();
    scatter_kernel<<<(NTOK + 255) / 256, 256>>>();
    dim3 g(MAX_TILES, ODIM / BN);
    moe_gemm_kernel<<<g, GEMM_THREADS, SMEM_TOTAL>>>(be, out);
}

// round 7
// speedup vs baseline: 1.1707x; 1.1707x over previous
#include <cuda_runtime.h>
#include <cuda_fp16.h>
#include <math.h>
#include <stdint.h>

// Problem constants
#define NTOK   8192
#define DIM    1024
#define ODIM   1024
#define NEXP   8
#define TOPK   2
#define ASSIGN (NTOK*TOPK)

// GEMM tiling
#define BM 128
#define BN 256
#define BK 64
#define NSTAGE (DIM/BK)                 // 16
#define MAX_TILES (ASSIGN/BM + NEXP)    // 136
#define GEMM_THREADS 256                // 8 warps: 2 (m) x 4 (n), warp tile 64x64

// ---- smem layout (bytes) ----
#define A_STRIDE_B 144
#define A_BUF      (128*A_STRIDE_B)     // 18432
#define A_OFF      0
#define B_STRIDE_B 528
#define B_BUF      (64*B_STRIDE_B)      // 33792
#define B_OFF      (2*A_BUF)            // 36864
#define TOK_OFF    (B_OFF + 2*B_BUF)    // 104448
#define GATE_OFF   (TOK_OFF + 512)
#define BE_OFF     (GATE_OFF + 512)
#define SMEM_TOTAL (BE_OFF + 1024)      // 106496

// gate tiling
#define GT_TOK 32
#define GT_CD  128
#define GT_PAD 136                      // padded fp32 stride (x4B = 544, 16B aligned)

// ---------------- device scratch ----------------
__device__ int   g_topk_idx[ASSIGN];
__device__ float g_topk_gate[ASSIGN];
__device__ int   g_counts[NEXP];
__device__ int   g_cursor[NEXP];
__device__ int   g_tile_expert[MAX_TILES];
__device__ int   g_tile_row[MAX_TILES];
__device__ int   g_tile_rows[MAX_TILES];
__device__ int   g_num_tiles;
__device__ int   g_assign_token[ASSIGN];
__device__ float g_assign_gate[ASSIGN];
// fp16 operands (x: [tok][k], W: [e][k][n])
__device__ __half g_xf[NTOK*DIM];
__device__ __half g_Wf[NEXP*DIM*ODIM];

// ---------------- PTX helpers (baseline PTX only) ----------------
__device__ __forceinline__ uint32_t smem_u32(const void* p) {
    uint32_t a;
    asm("{ .reg .u64 t; cvta.to.shared.u64 t, %1; cvt.u32.u64 %0, t; }" : "=r"(a) : "l"(p));
    return a;
}
__device__ __forceinline__ void cp16(uint32_t dst, const void* src) {
    asm volatile("cp.async.cg.shared.global [%0], [%1], 16;" :: "r"(dst), "l"(src));
}
#define CP_COMMIT() asm volatile("cp.async.commit_group;" ::: "memory")
#define CP_WAIT0()  asm volatile("cp.async.wait_group 0;" ::: "memory")

__device__ __forceinline__ void ldsm_x4(uint32_t* r, uint32_t addr) {
    asm volatile("ldmatrix.sync.aligned.m8n8.x4.shared.b16 {%0,%1,%2,%3}, [%4];"
        : "=r"(r[0]), "=r"(r[1]), "=r"(r[2]), "=r"(r[3]) : "r"(addr));
}
__device__ __forceinline__ void ldsm_x4_t(uint32_t* r, uint32_t addr) {
    asm volatile("ldmatrix.sync.aligned.m8n8.x4.trans.shared.b16 {%0,%1,%2,%3}, [%4];"
        : "=r"(r[0]), "=r"(r[1]), "=r"(r[2]), "=r"(r[3]) : "r"(addr));
}
__device__ __forceinline__ void mma_f16(float* c, const uint32_t* a, const uint32_t* b) {
    asm volatile(
        "mma.sync.aligned.m16n8k16.row.col.f32.f16.f16.f32 "
        "{%0,%1,%2,%3}, {%4,%5,%6,%7}, {%8,%9}, {%0,%1,%2,%3};"
        : "+f"(c[0]), "+f"(c[1]), "+f"(c[2]), "+f"(c[3])
        : "r"(a[0]), "r"(a[1]), "r"(a[2]), "r"(a[3]), "r"(b[0]), "r"(b[1]));
}

// ---------------- init: zero counters + zero output ----------------
__global__ void init_kernel(float* __restrict__ out, int out_elems)
{
    int t = blockIdx.x * blockDim.x + threadIdx.x;
    if (t < NEXP) g_counts[t] = 0;
    if (t == 0)   g_num_tiles = 0;
    int stride = gridDim.x * blockDim.x;
    float4 z = make_float4(0.f, 0.f, 0.f, 0.f);
    for (int i = t; i < out_elems / 4; i += stride)
        reinterpret_cast<float4*>(out)[i] = z;
}

// ---------------- convert x / We to fp16 ----------------
__global__ void convx_kernel(const float* __restrict__ x)
{
    int i = blockIdx.x * blockDim.x + threadIdx.x;
    if (i >= NTOK * DIM / 4) return;
    float4 v = reinterpret_cast<const float4*>(x)[i];
    __half2* o = reinterpret_cast<__half2*>(g_xf);
    o[i*2+0] = __floats2half2_rn(v.x, v.y);
    o[i*2+1] = __floats2half2_rn(v.z, v.w);
}
__global__ void convw_kernel(const float* __restrict__ We)
{
    int i = blockIdx.x * blockDim.x + threadIdx.x;
    if (i >= NEXP * DIM * ODIM / 4) return;
    float4 v = reinterpret_cast<const float4*>(We)[i];
    __half2* o = reinterpret_cast<__half2*>(g_Wf);
    o[i*2+0] = __floats2half2_rn(v.x, v.y);
    o[i*2+1] = __floats2half2_rn(v.z, v.w);
}

// ---------------- gating: smem-staged, coalesced ----------------
// 256 threads = 32 tokens x 8 experts. Stage x[32][128] and ws[8][128]
// (transposed Wg chunk) in smem with coalesced float4 GMEM loads; each
// thread accumulates its (token, expert) dot product from smem.
__global__ void gate_kernel(const float* __restrict__ x,
                            const float* __restrict__ Wg,
                            const float* __restrict__ bg)
{
    __shared__ float xs[GT_TOK][GT_PAD];
    __shared__ float ws[NEXP][GT_PAD];

    int t   = threadIdx.x;
    int tok = t >> 3;
    int e   = t & 7;
    int n0  = blockIdx.x * GT_TOK;
    int n   = n0 + tok;

    float acc0 = 0.f, acc1 = 0.f;

    for (int d0 = 0; d0 < DIM; d0 += GT_CD) {
        __syncthreads();
        // stage x: 32 tokens x 128 floats = 1024 float4, coalesced
        #pragma unroll
        for (int i = t; i < GT_TOK * GT_CD / 4; i += 256) {
            int tk = i >> 5;          // 32 float4 per token row
            int d4 = i & 31;
            float4 v = *reinterpret_cast<const float4*>(
                x + (size_t)(n0 + tk) * DIM + d0 + d4 * 4);
            xs[tk][d4*4+0] = v.x; xs[tk][d4*4+1] = v.y;
            xs[tk][d4*4+2] = v.z; xs[tk][d4*4+3] = v.w;
        }
        // stage ws (transpose): Wg[(d0+d)*8+e] -> ws[e][d]; coalesced read
        #pragma unroll
        for (int i = t; i < GT_CD * NEXP; i += 256) {
            int d = i >> 3, ee = i & 7;
            ws[ee][d] = Wg[(size_t)(d0 + d) * NEXP + ee];
        }
        __syncthreads();
        #pragma unroll
        for (int d = 0; d < GT_CD; d += 8) {
            float4 xv0 = *reinterpret_cast<const float4*>(&xs[tok][d]);
            float4 wv0 = *reinterpret_cast<const float4*>(&ws[e][d]);
            float4 xv1 = *reinterpret_cast<const float4*>(&xs[tok][d+4]);
            float4 wv1 = *reinterpret_cast<const float4*>(&ws[e][d+4]);
            acc0 += xv0.x*wv0.x + xv0.y*wv0.y + xv0.z*wv0.z + xv0.w*wv0.w;
            acc1 += xv1.x*wv1.x + xv1.y*wv1.y + xv1.z*wv1.z + xv1.w*wv1.w;
        }
    }
    float v = acc0 + acc1 + bg[e];

    int idx = e;
    float bv = v;  int bi = idx;
    #pragma unroll
    for (int off = 4; off; off >>= 1) {
        float ov = __shfl_xor_sync(0xffffffffu, bv, off);
        int   oi = __shfl_xor_sync(0xffffffffu, bi, off);
        if (ov > bv || (ov == bv && oi < bi)) { bv = ov; bi = oi; }
    }
    float sv = (idx == bi) ? -INFINITY : v;
    int   si = idx;
    #pragma unroll
    for (int off = 4; off; off >>= 1) {
        float ov = __shfl_xor_sync(0xffffffffu, sv, off);
        int   oi = __shfl_xor_sync(0xffffffffu, si, off);
        if (ov > sv || (ov == sv && oi < si)) { sv = ov; si = oi; }
    }
    if (e == 0) {
        float w1 = 1.0f / (1.0f + expf(sv - bv));
        float w2 = 1.0f - w1;
        g_topk_idx [n * 2 + 0] = bi;
        g_topk_idx [n * 2 + 1] = si;
        g_topk_gate[n * 2 + 0] = w1;
        g_topk_gate[n * 2 + 1] = w2;
        atomicAdd(&g_counts[bi], 1);
        atomicAdd(&g_counts[si], 1);
    }
}

// ---------------- scheduler + scatter ----------------
__global__ void sched_kernel()
{
    if (threadIdx.x != 0 || blockIdx.x != 0) return;
    int off = 0, nt = 0;
    for (int e = 0; e < NEXP; e++) {
        g_cursor[e] = off;
        int c = g_counts[e];
        for (int r = 0; r < c; r += BM) {
            g_tile_expert[nt] = e;
            g_tile_row[nt]    = off + r;
            g_tile_rows[nt]   = min(BM, c - r);
            nt++;
        }
        off += c;
    }
    g_num_tiles = nt;
}

__global__ void scatter_kernel()
{
    int n = blockIdx.x * blockDim.x + threadIdx.x;
    if (n >= NTOK) return;
    #pragma unroll
    for (int k = 0; k < TOPK; k++) {
        int   e = g_topk_idx [n * 2 + k];
        float g = g_topk_gate[n * 2 + k];
        int pos = atomicAdd(&g_cursor[e], 1);
        g_assign_token[pos] = n;
        g_assign_gate[pos]  = g;
    }
}

// ---------------- fp16 HMMA grouped GEMM (unchanged from R5) ----------------
__device__ __forceinline__ void load_stage(uint32_t sm, int k0, int buf,
                                           int e, int n0, const int* s_tok)
{
    int t = threadIdx.x;
    uint32_t abase = sm + A_OFF + buf * A_BUF;
    uint32_t bbase = sm + B_OFF + buf * B_BUF;
    #pragma unroll
    for (int c = t; c < 1024; c += GEMM_THREADS) {
        int r = c >> 3, c8 = c & 7;
        int tok = s_tok[r];
        size_t off = ((size_t)tok << 10) + k0 + (c8 << 3);
        cp16(abase + r * A_STRIDE_B + c8 * 16, g_xf + off);
    }
    #pragma unroll
    for (int c = t; c < 2048; c += GEMM_THREADS) {
        int kr = c >> 5, c32 = c & 31;
        size_t off = ((size_t)(e * DIM + k0 + kr) << 10) + n0 + (c32 << 3);
        cp16(bbase + kr * B_STRIDE_B + c32 * 16, g_Wf + off);
    }
    CP_COMMIT();
}

__global__ __launch_bounds__(GEMM_THREADS)
void moe_gemm_kernel(const float* __restrict__ be, float* __restrict__ out)
{
    extern __shared__ char dsm[];
    uint32_t sm = smem_u32(dsm);
    int tile = blockIdx.x;
    if (tile >= g_num_tiles) return;
    int e    = g_tile_expert[tile];
    int row0 = g_tile_row[tile];
    int rows = g_tile_rows[tile];
    int n0   = blockIdx.y * BN;
    int t    = threadIdx.x;
    int wid  = t >> 5, lane = t & 31;
    int wm   = wid & 1;
    int wn   = wid >> 1;

    int*   s_tok  = (int*)  (dsm + TOK_OFF);
    float* s_gate = (float*)(dsm + GATE_OFF);
    float* s_be   = (float*)(dsm + BE_OFF);

    if (t < BM) {
        if (t < rows) {
            s_tok [t] = g_assign_token[row0 + t];
            s_gate[t] = g_assign_gate [row0 + t];
        } else {
            s_tok [t] = 0;
            s_gate[t] = 0.f;
        }
    }
    s_be[t] = be[e * ODIM + n0 + t];
    __syncthreads();

    float acc[4][8][4];
    #pragma unroll
    for (int i = 0; i < 4; i++)
        #pragma unroll
        for (int j = 0; j < 8; j++)
            #pragma unroll
            for (int q = 0; q < 4; q++) acc[i][j][q] = 0.f;

    load_stage(sm, 0, 0, e, n0, s_tok);

    #pragma unroll 1
    for (int s = 0; s < NSTAGE; s++) {
        int buf = s & 1;
        CP_WAIT0();
        __syncthreads();
        if (s + 1 < NSTAGE)
            load_stage(sm, (s + 1) * BK, buf ^ 1, e, n0, s_tok);

        uint32_t abase = sm + A_OFF + buf * A_BUF;
        uint32_t bbase = sm + B_OFF + buf * B_BUF;
        #pragma unroll
        for (int ks = 0; ks < 4; ks++) {
            uint32_t a[4][4], b[8][2];
            #pragma unroll
            for (int mi = 0; mi < 4; mi++) {
                int row = wm * 64 + mi * 16 + (lane & 15);
                ldsm_x4(a[mi], abase + row * A_STRIDE_B + ks * 32 + (lane >> 4) * 16);
            }
            #pragma unroll
            for (int np = 0; np < 4; np++) {
                int krow = ks * 16 + (lane & 15);
                int ncol = wn * 64 + np * 16 + (lane >> 4) * 8;
                uint32_t tb[4];
                ldsm_x4_t(tb, bbase + krow * B_STRIDE_B + ncol * 2);
                b[np*2][0]   = tb[0]; b[np*2][1]   = tb[1];
                b[np*2+1][0] = tb[2]; b[np*2+1][1] = tb[3];
            }
            #pragma unroll
            for (int mi = 0; mi < 4; mi++)
                #pragma unroll
                for (int ni = 0; ni < 8; ni++)
                    mma_f16(acc[mi][ni], a[mi], b[ni]);
        }
        __syncthreads();
    }

    int r_in  = lane >> 2;
    int c_in  = (lane & 3) * 2;
    #pragma unroll
    for (int mi = 0; mi < 4; mi++) {
        int rbase = wm * 64 + mi * 16 + r_in;
        int tok0 = s_tok[rbase];     float g0 = s_gate[rbase];
        int tok1 = s_tok[rbase + 8]; float g1 = s_gate[rbase + 8];
        float* o0 = out + (size_t)tok0 * ODIM + n0;
        float* o1 = out + (size_t)tok1 * ODIM + n0;
        #pragma unroll
        for (int ni = 0; ni < 8; ni++) {
            int col = wn * 64 + ni * 8 + c_in;
            float b0 = s_be[col], b1 = s_be[col + 1];
            if (g0 != 0.f) {
                atomicAdd(o0 + col,     g0 * (acc[mi][ni][0] + b0));
                atomicAdd(o0 + col + 1, g0 * (acc[mi][ni][1] + b1));
            }
            if (g1 != 0.f) {
                atomicAdd(o1 + col,     g1 * (acc[mi][ni][2] + b0));
                atomicAdd(o1 + col + 1, g1 * (acc[mi][ni][3] + b1));
            }
        }
    }
}

// ---------------- launch ----------------
extern "C" void kernel_launch(void* const* d_in, const int* in_sizes, int n_in,
                              void* d_out, int out_size)
{
    const float* x  = (const float*)d_in[0];
    const float* We = (const float*)d_in[1];
    const float* be = (const float*)d_in[2];
    const float* Wg = (const float*)d_in[3];
    const float* bg = (const float*)d_in[4];
    float* out = (float*)d_out;

    static int smem_set = 0;
    if (!smem_set) {
        cudaFuncSetAttribute(moe_gemm_kernel,
                             cudaFuncAttributeMaxDynamicSharedMemorySize, SMEM_TOTAL);
        smem_set = 1;
    }

    init_kernel<<<512, 256>>>(out, out_size);
    convx_kernel<<<(NTOK * DIM / 4 + 255) / 256, 256>>>(x);
    convw_kernel<<<(NEXP * DIM * ODIM / 4 + 255) / 256, 256>>>(We);
    gate_kernel<<<NTOK / GT_TOK, 256>>>(x, Wg, bg);
    sched_kernel<<<1, 32>>>();
    scatter_kernel<<<(NTOK + 255) / 256, 256>>>();
    dim3 g(MAX_TILES, ODIM / BN);
    moe_gemm_kernel<<<g, GEMM_THREADS, SMEM_TOTAL>>>(be, out);
}

// round 8
// speedup vs baseline: 1.2461x; 1.0644x over previous
#include <cuda_runtime.h>
#include <cuda_fp16.h>
#include <math.h>
#include <stdint.h>

// Problem constants
#define NTOK   8192
#define DIM    1024
#define ODIM   1024
#define NEXP   8
#define TOPK   2
#define ASSIGN (NTOK*TOPK)

// GEMM tiling
#define BM 128
#define BN 256
#define BK 64
#define NSTAGE (DIM/BK)                 // 16
#define MAX_TILES (ASSIGN/BM + NEXP)    // 136
#define GEMM_THREADS 256                // 8 warps: 2 (m) x 4 (n), warp tile 64x64

// ---- smem layout (bytes), 3-stage pipeline ----
#define A_STRIDE_B 144
#define A_BUF      (128*A_STRIDE_B)     // 18432
#define A_OFF      0
#define B_STRIDE_B 528
#define B_BUF      (64*B_STRIDE_B)      // 33792
#define B_OFF      (3*A_BUF)            // 55296
#define TOK_OFF    (B_OFF + 3*B_BUF)    // 156672
#define GATE_OFF   (TOK_OFF + 512)
#define BE_OFF     (GATE_OFF + 512)
#define SMEM_TOTAL (BE_OFF + 1024)      // 158720

// gate tiling
#define GT_TOK 16
#define GT_CD  128
#define GT_PAD 132                      // 132 mod 32 = 4 -> conflict-free ws reads

// ---------------- device scratch ----------------
__device__ int   g_topk_idx[ASSIGN];
__device__ float g_topk_gate[ASSIGN];
__device__ int   g_counts[NEXP];
__device__ int   g_cursor[NEXP];
__device__ int   g_tile_expert[MAX_TILES];
__device__ int   g_tile_row[MAX_TILES];
__device__ int   g_tile_rows[MAX_TILES];
__device__ int   g_num_tiles;
__device__ int   g_assign_token[ASSIGN];
__device__ float g_assign_gate[ASSIGN];
// fp16 operands (x: [tok][k], W: [e][k][n])
__device__ __half g_xf[NTOK*DIM];
__device__ __half g_Wf[NEXP*DIM*ODIM];

// ---------------- PTX helpers (baseline PTX only) ----------------
__device__ __forceinline__ uint32_t smem_u32(const void* p) {
    uint32_t a;
    asm("{ .reg .u64 t; cvta.to.shared.u64 t, %1; cvt.u32.u64 %0, t; }" : "=r"(a) : "l"(p));
    return a;
}
__device__ __forceinline__ void cp16(uint32_t dst, const void* src) {
    asm volatile("cp.async.cg.shared.global [%0], [%1], 16;" :: "r"(dst), "l"(src));
}
#define CP_COMMIT() asm volatile("cp.async.commit_group;" ::: "memory")
#define CP_WAIT(N)  asm volatile("cp.async.wait_group %0;" :: "n"(N) : "memory")

__device__ __forceinline__ void ldsm_x4(uint32_t* r, uint32_t addr) {
    asm volatile("ldmatrix.sync.aligned.m8n8.x4.shared.b16 {%0,%1,%2,%3}, [%4];"
        : "=r"(r[0]), "=r"(r[1]), "=r"(r[2]), "=r"(r[3]) : "r"(addr));
}
__device__ __forceinline__ void ldsm_x4_t(uint32_t* r, uint32_t addr) {
    asm volatile("ldmatrix.sync.aligned.m8n8.x4.trans.shared.b16 {%0,%1,%2,%3}, [%4];"
        : "=r"(r[0]), "=r"(r[1]), "=r"(r[2]), "=r"(r[3]) : "r"(addr));
}
__device__ __forceinline__ void mma_f16(float* c, const uint32_t* a, const uint32_t* b) {
    asm volatile(
        "mma.sync.aligned.m16n8k16.row.col.f32.f16.f16.f32 "
        "{%0,%1,%2,%3}, {%4,%5,%6,%7}, {%8,%9}, {%0,%1,%2,%3};"
        : "+f"(c[0]), "+f"(c[1]), "+f"(c[2]), "+f"(c[3])
        : "r"(a[0]), "r"(a[1]), "r"(a[2]), "r"(a[3]), "r"(b[0]), "r"(b[1]));
}

// ---------------- init: zero counters + zero output ----------------
__global__ void init_kernel(float* __restrict__ out, int out_elems)
{
    int t = blockIdx.x * blockDim.x + threadIdx.x;
    if (t < NEXP) g_counts[t] = 0;
    if (t == 0)   g_num_tiles = 0;
    int stride = gridDim.x * blockDim.x;
    float4 z = make_float4(0.f, 0.f, 0.f, 0.f);
    for (int i = t; i < out_elems / 4; i += stride)
        reinterpret_cast<float4*>(out)[i] = z;
}

// ---------------- convert We to fp16 ----------------
__global__ void convw_kernel(const float* __restrict__ We)
{
    int i = blockIdx.x * blockDim.x + threadIdx.x;
    if (i >= NEXP * DIM * ODIM / 4) return;
    float4 v = reinterpret_cast<const float4*>(We)[i];
    __half2* o = reinterpret_cast<__half2*>(g_Wf);
    o[i*2+0] = __floats2half2_rn(v.x, v.y);
    o[i*2+1] = __floats2half2_rn(v.z, v.w);
}

// ---------------- fused gate + x->fp16 conversion ----------------
// 256 threads = 16 tokens x (8 experts x 2 D-halves). Stage x[16][128] in
// smem (coalesced) AND emit the fp16 copy of x in the same pass; stage
// transposed Wg chunk. Each thread dots a 64-wide slice; shfl folds halves.
__global__ void gate_kernel(const float* __restrict__ x,
                            const float* __restrict__ Wg,
                            const float* __restrict__ bg)
{
    __shared__ float xs[GT_TOK][GT_PAD];
    __shared__ float ws[NEXP][GT_PAD];

    int t   = threadIdx.x;
    int n0  = blockIdx.x * GT_TOK;
    int tok = t >> 4;          // 0..15
    int sub = t & 15;
    int e   = sub & 7;
    int h   = sub >> 3;        // D-half

    float acc = 0.f;

    for (int d0 = 0; d0 < DIM; d0 += GT_CD) {
        __syncthreads();
        // stage x (coalesced float4) + write fp16 copy
        #pragma unroll
        for (int i = t; i < GT_TOK * GT_CD / 4; i += 256) {
            int tk = i >> 5, d4 = i & 31;
            size_t goff = (size_t)(n0 + tk) * DIM + d0 + d4 * 4;
            float4 v = *reinterpret_cast<const float4*>(x + goff);
            xs[tk][d4*4+0] = v.x; xs[tk][d4*4+1] = v.y;
            xs[tk][d4*4+2] = v.z; xs[tk][d4*4+3] = v.w;
            __half2* o = reinterpret_cast<__half2*>(g_xf + goff);
            o[0] = __floats2half2_rn(v.x, v.y);
            o[1] = __floats2half2_rn(v.z, v.w);
        }
        // stage ws (transpose): Wg[(d0+d)*8+e] -> ws[e][d]; coalesced read
        #pragma unroll
        for (int i = t; i < GT_CD * NEXP; i += 256) {
            int d = i >> 3, ee = i & 7;
            ws[ee][d] = Wg[(size_t)(d0 + d) * NEXP + ee];
        }
        __syncthreads();
        const float* xp = &xs[tok][h * 64];
        const float* wp = &ws[e][h * 64];
        #pragma unroll
        for (int d = 0; d < 64; d += 4) {
            float4 xv = *reinterpret_cast<const float4*>(xp + d);
            float4 wv = *reinterpret_cast<const float4*>(wp + d);
            acc += xv.x*wv.x + xv.y*wv.y + xv.z*wv.z + xv.w*wv.w;
        }
    }
    // fold the two D-halves (lane bit 3 = h), add bias
    float v = acc + __shfl_xor_sync(0xffffffffu, acc, 8) + bg[e];

    int idx = e;
    float bv = v;  int bi = idx;
    #pragma unroll
    for (int off = 4; off; off >>= 1) {
        float ov = __shfl_xor_sync(0xffffffffu, bv, off);
        int   oi = __shfl_xor_sync(0xffffffffu, bi, off);
        if (ov > bv || (ov == bv && oi < bi)) { bv = ov; bi = oi; }
    }
    float sv = (idx == bi) ? -INFINITY : v;
    int   si = idx;
    #pragma unroll
    for (int off = 4; off; off >>= 1) {
        float ov = __shfl_xor_sync(0xffffffffu, sv, off);
        int   oi = __shfl_xor_sync(0xffffffffu, si, off);
        if (ov > sv || (ov == sv && oi < si)) { sv = ov; si = oi; }
    }
    if (sub == 0) {
        int n = n0 + tok;
        float w1 = 1.0f / (1.0f + expf(sv - bv));
        float w2 = 1.0f - w1;
        g_topk_idx [n * 2 + 0] = bi;
        g_topk_idx [n * 2 + 1] = si;
        g_topk_gate[n * 2 + 0] = w1;
        g_topk_gate[n * 2 + 1] = w2;
        atomicAdd(&g_counts[bi], 1);
        atomicAdd(&g_counts[si], 1);
    }
}

// ---------------- scheduler + scatter ----------------
__global__ void sched_kernel()
{
    if (threadIdx.x != 0 || blockIdx.x != 0) return;
    int off = 0, nt = 0;
    for (int e = 0; e < NEXP; e++) {
        g_cursor[e] = off;
        int c = g_counts[e];
        for (int r = 0; r < c; r += BM) {
            g_tile_expert[nt] = e;
            g_tile_row[nt]    = off + r;
            g_tile_rows[nt]   = min(BM, c - r);
            nt++;
        }
        off += c;
    }
    g_num_tiles = nt;
}

__global__ void scatter_kernel()
{
    int n = blockIdx.x * blockDim.x + threadIdx.x;
    if (n >= NTOK) return;
    #pragma unroll
    for (int k = 0; k < TOPK; k++) {
        int   e = g_topk_idx [n * 2 + k];
        float g = g_topk_gate[n * 2 + k];
        int pos = atomicAdd(&g_cursor[e], 1);
        g_assign_token[pos] = n;
        g_assign_gate[pos]  = g;
    }
}

// ---------------- fp16 HMMA grouped GEMM, 3-stage cp.async pipeline ----------------
__device__ __forceinline__ void load_stage(uint32_t sm, int k0, int buf,
                                           int e, int n0, const int* s_tok)
{
    int t = threadIdx.x;
    uint32_t abase = sm + A_OFF + buf * A_BUF;
    uint32_t bbase = sm + B_OFF + buf * B_BUF;
    #pragma unroll
    for (int c = t; c < 1024; c += GEMM_THREADS) {
        int r = c >> 3, c8 = c & 7;
        int tok = s_tok[r];
        size_t off = ((size_t)tok << 10) + k0 + (c8 << 3);
        cp16(abase + r * A_STRIDE_B + c8 * 16, g_xf + off);
    }
    #pragma unroll
    for (int c = t; c < 2048; c += GEMM_THREADS) {
        int kr = c >> 5, c32 = c & 31;
        size_t off = ((size_t)(e * DIM + k0 + kr) << 10) + n0 + (c32 << 3);
        cp16(bbase + kr * B_STRIDE_B + c32 * 16, g_Wf + off);
    }
    CP_COMMIT();
}

__global__ __launch_bounds__(GEMM_THREADS)
void moe_gemm_kernel(const float* __restrict__ be, float* __restrict__ out)
{
    extern __shared__ char dsm[];
    uint32_t sm = smem_u32(dsm);
    int tile = blockIdx.x;
    if (tile >= g_num_tiles) return;
    int e    = g_tile_expert[tile];
    int row0 = g_tile_row[tile];
    int rows = g_tile_rows[tile];
    int n0   = blockIdx.y * BN;
    int t    = threadIdx.x;
    int wid  = t >> 5, lane = t & 31;
    int wm   = wid & 1;
    int wn   = wid >> 1;

    int*   s_tok  = (int*)  (dsm + TOK_OFF);
    float* s_gate = (float*)(dsm + GATE_OFF);
    float* s_be   = (float*)(dsm + BE_OFF);

    if (t < BM) {
        if (t < rows) {
            s_tok [t] = g_assign_token[row0 + t];
            s_gate[t] = g_assign_gate [row0 + t];
        } else {
            s_tok [t] = 0;
            s_gate[t] = 0.f;
        }
    }
    s_be[t] = be[e * ODIM + n0 + t];
    __syncthreads();

    float acc[4][8][4];
    #pragma unroll
    for (int i = 0; i < 4; i++)
        #pragma unroll
        for (int j = 0; j < 8; j++)
            #pragma unroll
            for (int q = 0; q < 4; q++) acc[i][j][q] = 0.f;

    // prologue: 2 stages in flight
    load_stage(sm, 0,  0, e, n0, s_tok);
    load_stage(sm, BK, 1, e, n0, s_tok);

    #pragma unroll 1
    for (int s = 0; s < NSTAGE; s++) {
        int buf = s % 3;
        if (s == NSTAGE - 1) { CP_WAIT(0); } else { CP_WAIT(1); }
        __syncthreads();   // all threads' stage-s data resident; prior compute done
        if (s + 2 < NSTAGE)
            load_stage(sm, (s + 2) * BK, (s + 2) % 3, e, n0, s_tok);

        uint32_t abase = sm + A_OFF + buf * A_BUF;
        uint32_t bbase = sm + B_OFF + buf * B_BUF;
        #pragma unroll
        for (int ks = 0; ks < 4; ks++) {
            uint32_t a[4][4], b[8][2];
            #pragma unroll
            for (int mi = 0; mi < 4; mi++) {
                int row = wm * 64 + mi * 16 + (lane & 15);
                ldsm_x4(a[mi], abase + row * A_STRIDE_B + ks * 32 + (lane >> 4) * 16);
            }
            #pragma unroll
            for (int np = 0; np < 4; np++) {
                int krow = ks * 16 + (lane & 15);
                int ncol = wn * 64 + np * 16 + (lane >> 4) * 8;
                uint32_t tb[4];
                ldsm_x4_t(tb, bbase + krow * B_STRIDE_B + ncol * 2);
                b[np*2][0]   = tb[0]; b[np*2][1]   = tb[1];
                b[np*2+1][0] = tb[2]; b[np*2+1][1] = tb[3];
            }
            #pragma unroll
            for (int mi = 0; mi < 4; mi++)
                #pragma unroll
                for (int ni = 0; ni < 8; ni++)
                    mma_f16(acc[mi][ni], a[mi], b[ni]);
        }
    }

    int r_in  = lane >> 2;
    int c_in  = (lane & 3) * 2;
    #pragma unroll
    for (int mi = 0; mi < 4; mi++) {
        int rbase = wm * 64 + mi * 16 + r_in;
        int tok0 = s_tok[rbase];     float g0 = s_gate[rbase];
        int tok1 = s_tok[rbase + 8]; float g1 = s_gate[rbase + 8];
        float* o0 = out + (size_t)tok0 * ODIM + n0;
        float* o1 = out + (size_t)tok1 * ODIM + n0;
        #pragma unroll
        for (int ni = 0; ni < 8; ni++) {
            int col = wn * 64 + ni * 8 + c_in;
            float b0 = s_be[col], b1 = s_be[col + 1];
            if (g0 != 0.f) {
                atomicAdd(o0 + col,     g0 * (acc[mi][ni][0] + b0));
                atomicAdd(o0 + col + 1, g0 * (acc[mi][ni][1] + b1));
            }
            if (g1 != 0.f) {
                atomicAdd(o1 + col,     g1 * (acc[mi][ni][2] + b0));
                atomicAdd(o1 + col + 1, g1 * (acc[mi][ni][3] + b1));
            }
        }
    }
}

// ---------------- launch ----------------
extern "C" void kernel_launch(void* const* d_in, const int* in_sizes, int n_in,
                              void* d_out, int out_size)
{
    const float* x  = (const float*)d_in[0];
    const float* We = (const float*)d_in[1];
    const float* be = (const float*)d_in[2];
    const float* Wg = (const float*)d_in[3];
    const float* bg = (const float*)d_in[4];
    float* out = (float*)d_out;

    static int smem_set = 0;
    if (!smem_set) {
        cudaFuncSetAttribute(moe_gemm_kernel,
                             cudaFuncAttributeMaxDynamicSharedMemorySize, SMEM_TOTAL);
        smem_set = 1;
    }

    init_kernel<<<512, 256>>>(out, out_size);
    convw_kernel<<<(NEXP * DIM * ODIM / 4 + 255) / 256, 256>>>(We);
    gate_kernel<<<NTOK / GT_TOK, 256>>>(x, Wg, bg);
    sched_kernel<<<1, 32>>>();
    scatter_kernel<<<(NTOK + 255) / 256, 256>>>();
    dim3 g(MAX_TILES, ODIM / BN);
    moe_gemm_kernel<<<g, GEMM_THREADS, SMEM_TOTAL>>>(be, out);
}